// round 13
// baseline (speedup 1.0000x reference)
#include <cuda_runtime.h>
#include <cuda_fp16.h>
#include <cstdint>
#include <math.h>

// ---------------------------------------------------------------------------
// Problem constants
// ---------------------------------------------------------------------------
#define HIMG   56
#define WSZ    7
#define SSZ    3
#define DIM    384
#define HEADS  12
#define HDIM   32
#define NBATCH 16
#define NTOK   (NBATCH * HIMG * HIMG)     // 50176 rows
#define NWIMG  64
#define NWIN   (NBATCH * NWIMG)           // 1024 windows
#define NT     49                         // tokens per window

// ---------------------------------------------------------------------------
// Static scratch
// ---------------------------------------------------------------------------
__device__ __half g_Awin[(size_t)NTOK * DIM];
__device__ __half g_Qh[(size_t)NTOK * DIM];
__device__ __half g_Kh[(size_t)NTOK * DIM];
__device__ __half g_Vh[(size_t)NTOK * DIM];
__device__ __half g_O[(size_t)NTOK * DIM];
__device__ __half g_A2[(size_t)NTOK * DIM];
__device__ __half g_Hm[(size_t)NTOK * 4 * DIM];
__device__ __half g_Wqkv[DIM * 3 * DIM];
__device__ __half g_Wproj[DIM * DIM];
__device__ __half g_Wfc1[DIM * 4 * DIM];
__device__ __half g_Wfc2[4 * DIM * DIM];
__device__ float  g_T[(size_t)64 * 12 * 64 * 56];

// ---------------------------------------------------------------------------
// fused fp32 -> fp16 weight conversion (4 segments, 1 launch)
// ---------------------------------------------------------------------------
#define NQKV (DIM * 3 * DIM)
#define NPRJ (DIM * DIM)
#define NFC1 (DIM * 4 * DIM)
#define NFC2 (4 * DIM * DIM)
__global__ void f2h_all_kernel(const float* __restrict__ s0, const float* __restrict__ s1,
                               const float* __restrict__ s2, const float* __restrict__ s3,
                               __half* __restrict__ d0, __half* __restrict__ d1,
                               __half* __restrict__ d2, __half* __restrict__ d3) {
    int i = blockIdx.x * blockDim.x + threadIdx.x;
    if (i < NQKV) { d0[i] = __float2half(s0[i]); return; }
    i -= NQKV;
    if (i < NPRJ) { d1[i] = __float2half(s1[i]); return; }
    i -= NPRJ;
    if (i < NFC1) { d2[i] = __float2half(s2[i]); return; }
    i -= NFC1;
    if (i < NFC2) { d3[i] = __float2half(s3[i]); }
}

// ---------------------------------------------------------------------------
// bias+mask table build: T[wi][h][q][c]
// ---------------------------------------------------------------------------
__global__ void build_table(const float* __restrict__ rpb, const float* __restrict__ mask,
                            float* __restrict__ T) {
    int t = blockIdx.x * 256 + threadIdx.x;
    const int total = 64 * 12 * 64 * 56;
    if (t >= total) return;
    int c = t % 56;
    int tmp = t / 56;
    int q = tmp & 63; tmp >>= 6;
    int h = tmp % 12;
    int wi = tmp / 12;
    float v;
    if (q < 49 && c < 49) {
        int i1 = q / 7, j1 = q - 7 * i1;
        int i2 = c / 7, j2 = c - 7 * i2;
        int ridx = (i1 - i2 + 6) * 13 + (j1 - j2 + 6);
        v = rpb[ridx * 12 + h] + mask[((size_t)wi * 49 + q) * 49 + c];
    } else {
        v = (q < 49) ? -1e30f : 0.f;
    }
    T[t] = v;
}

// ---------------------------------------------------------------------------
// LayerNorm kernels
// ---------------------------------------------------------------------------
__device__ __forceinline__ float warp_sum(float v) {
#pragma unroll
    for (int o = 16; o > 0; o >>= 1) v += __shfl_xor_sync(0xFFFFFFFFu, v, o);
    return v;
}

__global__ void ln_gather_kernel(const float* __restrict__ x, const float* __restrict__ g,
                                 const float* __restrict__ b, __half* __restrict__ out) {
    int r = blockIdx.x * 4 + (threadIdx.x >> 5);
    int lane = threadIdx.x & 31;
    int w = r / NT, n = r - w * NT;
    int bimg = w >> 6, wi = w & 63;
    int wr = wi >> 3, wc = wi & 7;
    int i = n / WSZ, j = n - i * WSZ;
    int hh = wr * WSZ + i + SSZ; if (hh >= HIMG) hh -= HIMG;
    int ww = wc * WSZ + j + SSZ; if (ww >= HIMG) ww -= HIMG;
    size_t t = (size_t)bimg * (HIMG * HIMG) + hh * HIMG + ww;
    const float* xp = x + t * DIM;
    float v[12], s = 0.f;
#pragma unroll
    for (int k = 0; k < 12; k++) { v[k] = xp[lane + k * 32]; s += v[k]; }
    float mu = warp_sum(s) * (1.0f / DIM), s2 = 0.f;
#pragma unroll
    for (int k = 0; k < 12; k++) { float d0 = v[k] - mu; s2 += d0 * d0; }
    float rs = rsqrtf(warp_sum(s2) * (1.0f / DIM) + 1e-5f);
    __half* op = out + (size_t)r * DIM;
#pragma unroll
    for (int k = 0; k < 12; k++) {
        int c = lane + k * 32;
        op[c] = __float2half((v[k] - mu) * rs * g[c] + b[c]);
    }
}

__global__ void ln_plain_kernel(const float* __restrict__ x, const float* __restrict__ g,
                                const float* __restrict__ b, __half* __restrict__ out) {
    int r = blockIdx.x * 4 + (threadIdx.x >> 5);
    int lane = threadIdx.x & 31;
    const float* xp = x + (size_t)r * DIM;
    float v[12], s = 0.f;
#pragma unroll
    for (int k = 0; k < 12; k++) { v[k] = xp[lane + k * 32]; s += v[k]; }
    float mu = warp_sum(s) * (1.0f / DIM), s2 = 0.f;
#pragma unroll
    for (int k = 0; k < 12; k++) { float d0 = v[k] - mu; s2 += d0 * d0; }
    float rs = rsqrtf(warp_sum(s2) * (1.0f / DIM) + 1e-5f);
    __half* op = out + (size_t)r * DIM;
#pragma unroll
    for (int k = 0; k < 12; k++) {
        int c = lane + k * 32;
        op[c] = __float2half((v[k] - mu) * rs * g[c] + b[c]);
    }
}

// ---------------------------------------------------------------------------
// fp16 GEMM (mma.sync m16n8k16): 128x128x64 CTA tile, 512 threads (16 warps),
// warp tile 32x32 (acc = 32 regs), 2-stage cp.async pipeline (R12 structure).
// __launch_bounds__(512,2) -> 64 regs -> 2 CTAs/SM -> 32 warps/SM (50% occ).
// Epilogue consumes PAIRS: epi(r, c, v_c, v_{c+1}).
// ---------------------------------------------------------------------------
__device__ __forceinline__ unsigned smem_u32(const void* p) {
    return (unsigned)__cvta_generic_to_shared(p);
}

#define BKL       64
#define A_STRIDE  72                      // halves (144B row: conflict-free)
#define B_STRIDE  136                     // halves (272B row: conflict-free)
#define A_BYTES   (128 * A_STRIDE * 2)    // 18432
#define STAGE_B   (A_BYTES + BKL * B_STRIDE * 2)   // 35840
#define GEMM_SMEM (2 * STAGE_B)           // 71680

template <class Epi>
__global__ void __launch_bounds__(512, 2)
gemm_f16_kernel(const __half* __restrict__ A, const __half* __restrict__ Bw,
                int M, int N, int K, Epi epi) {
    extern __shared__ char smem[];
    const uint32_t sb = smem_u32(smem);

    const int tid = threadIdx.x;
    const int warp = tid >> 5, lane = tid & 31;
    const int wm = (warp >> 2) * 32;      // 4 warp-rows of 32
    const int wn = (warp & 3) * 32;       // 4 warp-cols of 32
    const int bm = blockIdx.y * 128;
    const int bn = blockIdx.x * 128;

    const __half* Abase = A + (size_t)bm * K;
    const __half* Bbase = Bw + bn;

    auto load_stage = [&](int st, int k0) {
        uint32_t abase = sb + st * STAGE_B;
        uint32_t bbase = abase + A_BYTES;
#pragma unroll
        for (int j = 0; j < 2; j++) {
            int idx = tid + j * 512;              // 0..1023
            int r = idx >> 3, c8 = (idx & 7) * 8; // A: 128 x 64
            unsigned d = abase + (r * A_STRIDE + c8) * 2;
            const void* s = Abase + (size_t)r * K + k0 + c8;
            asm volatile("cp.async.cg.shared.global [%0], [%1], 16;\n" :: "r"(d), "l"(s));
        }
#pragma unroll
        for (int j = 0; j < 2; j++) {
            int idx = tid + j * 512;
            int r = idx >> 4, c8 = (idx & 15) * 8; // B: 64 x 128
            unsigned d = bbase + (r * B_STRIDE + c8) * 2;
            const void* s = Bbase + (size_t)(k0 + r) * N + c8;
            asm volatile("cp.async.cg.shared.global [%0], [%1], 16;\n" :: "r"(d), "l"(s));
        }
    };

    float acc[2][4][4];
#pragma unroll
    for (int a = 0; a < 2; a++)
#pragma unroll
        for (int b = 0; b < 4; b++)
#pragma unroll
            for (int c = 0; c < 4; c++) acc[a][b][c] = 0.f;

    const int ktiles = K / BKL;

    load_stage(0, 0);
    asm volatile("cp.async.commit_group;\n");
    load_stage(1, BKL);
    asm volatile("cp.async.commit_group;\n");

    for (int i = 0; i < ktiles; i++) {
        asm volatile("cp.async.wait_group 1;\n");
        __syncthreads();

        const uint32_t abase = sb + (i & 1) * STAGE_B;
        const uint32_t bbase = abase + A_BYTES;

#pragma unroll
        for (int kk = 0; kk < BKL; kk += 16) {
            uint32_t af[2][4], bfx[2][4];
#pragma unroll
            for (int mi = 0; mi < 2; mi++) {
                unsigned addr = abase +
                    ((wm + mi * 16 + (lane & 15)) * A_STRIDE + kk + (lane >> 4) * 8) * 2;
                asm volatile(
                    "ldmatrix.sync.aligned.m8n8.x4.shared.b16 {%0,%1,%2,%3}, [%4];\n"
                    : "=r"(af[mi][0]), "=r"(af[mi][1]), "=r"(af[mi][2]), "=r"(af[mi][3])
                    : "r"(addr));
            }
            // B: two x4.trans loads, each covering a 16x16 block (two n8 tiles)
#pragma unroll
            for (int g = 0; g < 2; g++) {
                unsigned addr = bbase +
                    ((kk + (lane & 15)) * B_STRIDE + wn + g * 16 + (lane >> 4) * 8) * 2;
                asm volatile(
                    "ldmatrix.sync.aligned.m8n8.x4.trans.shared.b16 {%0,%1,%2,%3}, [%4];\n"
                    : "=r"(bfx[g][0]), "=r"(bfx[g][1]), "=r"(bfx[g][2]), "=r"(bfx[g][3])
                    : "r"(addr));
            }
#pragma unroll
            for (int mi = 0; mi < 2; mi++)
#pragma unroll
                for (int ni = 0; ni < 4; ni++) {
                    const int g = ni >> 1, hhalf = (ni & 1) * 2;
                    asm volatile(
                        "mma.sync.aligned.m16n8k16.row.col.f32.f16.f16.f32 "
                        "{%0,%1,%2,%3}, {%4,%5,%6,%7}, {%8,%9}, {%0,%1,%2,%3};\n"
                        : "+f"(acc[mi][ni][0]), "+f"(acc[mi][ni][1]),
                          "+f"(acc[mi][ni][2]), "+f"(acc[mi][ni][3])
                        : "r"(af[mi][0]), "r"(af[mi][1]), "r"(af[mi][2]), "r"(af[mi][3]),
                          "r"(bfx[g][hhalf]), "r"(bfx[g][hhalf + 1]));
                }
        }
        __syncthreads();    // compute done; buffer (i&1) free for reload

        if (i + 2 < ktiles) load_stage(i & 1, (i + 2) * BKL);
        asm volatile("cp.async.commit_group;\n");   // unconditional: keeps group count exact
    }

    const int r0 = bm + wm + (lane >> 2);
    const int c0 = bn + wn + (lane & 3) * 2;
#pragma unroll
    for (int mi = 0; mi < 2; mi++) {
#pragma unroll
        for (int ni = 0; ni < 4; ni++) {
            int rr = r0 + mi * 16;
            int cc = c0 + ni * 8;
            epi(rr,     cc, acc[mi][ni][0], acc[mi][ni][1]);
            epi(rr + 8, cc, acc[mi][ni][2], acc[mi][ni][3]);
        }
    }
}

// ---------------------------------------------------------------------------
// Epilogue functors — pair interface (c, c+1)
// ---------------------------------------------------------------------------
struct EpiQKV {
    const float* bias;
    __half *Qo, *Ko, *Vo;
    __device__ __forceinline__ void operator()(int r, int c, float v0, float v1) const {
        v0 += bias[c]; v1 += bias[c + 1];
        int which = c / DIM;
        int rem = c - which * DIM;
        int h = rem >> 5, d = rem & 31;
        int w = r / NT, n = r - w * NT;
        size_t dst = (((size_t)(w * HEADS + h)) * NT + n) * HDIM + d;
        __half2 hv = __floats2half2_rn(v0, v1);
        if (which == 0)      *(__half2*)&Qo[dst] = hv;
        else if (which == 1) *(__half2*)&Ko[dst] = hv;
        else                 *(__half2*)&Vo[dst] = hv;
    }
};

struct EpiProj {
    const float* bias;
    const float* x1;
    float* y1;
    __device__ __forceinline__ void operator()(int r, int c, float v0, float v1) const {
        int w = r / NT, n = r - w * NT;
        int bimg = w >> 6, wi = w & 63;
        int wr = wi >> 3, wc = wi & 7;
        int i = n / WSZ, j = n - i * WSZ;
        int hh = wr * WSZ + i + SSZ; if (hh >= HIMG) hh -= HIMG;
        int ww = wc * WSZ + j + SSZ; if (ww >= HIMG) ww -= HIMG;
        size_t t = (size_t)bimg * (HIMG * HIMG) + hh * HIMG + ww;
        size_t o = t * DIM + c;
        float2 xr = *(const float2*)&x1[o];
        float2 ov;
        ov.x = xr.x + v0 + bias[c];
        ov.y = xr.y + v1 + bias[c + 1];
        *(float2*)&y1[o] = ov;
    }
};

struct EpiGelu {
    const float* bias;
    __half* Ho;
    __device__ __forceinline__ void operator()(int r, int c, float v0, float v1) const {
        v0 += bias[c]; v1 += bias[c + 1];
        float g0 = 0.5f * v0 * (1.0f + erff(v0 * 0.70710678118654752f));
        float g1 = 0.5f * v1 * (1.0f + erff(v1 * 0.70710678118654752f));
        *(__half2*)&Ho[(size_t)r * (4 * DIM) + c] = __floats2half2_rn(g0, g1);
    }
};

struct EpiY2 {
    const float* bias;
    const float* x2;
    float* y2;
    __device__ __forceinline__ void operator()(int r, int c, float v0, float v1) const {
        size_t o = (size_t)r * DIM + c;
        float2 xr = *(const float2*)&x2[o];
        float2 ov;
        ov.x = xr.x + v0 + bias[c];
        ov.y = xr.y + v1 + bias[c + 1];
        *(float2*)&y2[o] = ov;
    }
};

// ---------------------------------------------------------------------------
// Tensor-core windowed attention (unchanged from R10/R12, measured good)
// ---------------------------------------------------------------------------
#define ATT_LDS 40

__global__ void __launch_bounds__(64)
attn_mma_kernel(const __half* __restrict__ Qg, const __half* __restrict__ Kg,
                const __half* __restrict__ Vg, const float* __restrict__ T,
                __half* __restrict__ O) {
    __shared__ __half sm[2][3][64 * ATT_LDS];

    const int warp = threadIdx.x >> 5, lane = threadIdx.x & 31;
    const int wh = blockIdx.x * 2 + warp;
    const int w = wh / HEADS, h = wh - w * HEADS;
    const int wi = w & 63;

    __half* Qs = sm[warp][0];
    __half* Ks = sm[warp][1];
    __half* Vs = sm[warp][2];

    const __half* gq = Qg + (size_t)wh * NT * HDIM;
    const __half* gk = Kg + (size_t)wh * NT * HDIM;
    const __half* gv = Vg + (size_t)wh * NT * HDIM;
    const uint4 zz = make_uint4(0u, 0u, 0u, 0u);
#pragma unroll
    for (int it = 0; it < 8; it++) {
        int idx = it * 32 + lane;
        int row = idx >> 2, ch = idx & 3;
        bool ok = row < NT;
        uint4 vq = ok ? *(const uint4*)(gq + (size_t)row * 32 + ch * 8) : zz;
        uint4 vk = ok ? *(const uint4*)(gk + (size_t)row * 32 + ch * 8) : zz;
        uint4 vv = ok ? *(const uint4*)(gv + (size_t)row * 32 + ch * 8) : zz;
        *(uint4*)(Qs + row * ATT_LDS + ch * 8) = vq;
        *(uint4*)(Ks + row * ATT_LDS + ch * 8) = vk;
        *(uint4*)(Vs + row * ATT_LDS + ch * 8) = vv;
    }
    __syncwarp();

    const float SCALE = 0.17677669529663687f;
    const float* Trow = T + (size_t)(wi * HEADS + h) * 64 * 56;
    const int r1 = lane >> 2;
    const int cb = (lane & 3) * 2;

#pragma unroll 1
    for (int mt = 0; mt < 4; mt++) {
        uint32_t aq[2][4];
#pragma unroll
        for (int kk = 0; kk < 2; kk++) {
            unsigned addr = smem_u32(Qs + (mt * 16 + (lane & 15)) * ATT_LDS +
                                     kk * 16 + (lane >> 4) * 8);
            asm volatile("ldmatrix.sync.aligned.m8n8.x4.shared.b16 {%0,%1,%2,%3}, [%4];\n"
                : "=r"(aq[kk][0]), "=r"(aq[kk][1]), "=r"(aq[kk][2]), "=r"(aq[kk][3])
                : "r"(addr));
        }

        float sacc[7][4];
#pragma unroll
        for (int nt = 0; nt < 7; nt++)
#pragma unroll
            for (int c = 0; c < 4; c++) sacc[nt][c] = 0.f;

#pragma unroll
        for (int kk = 0; kk < 2; kk++) {
#pragma unroll
            for (int nt = 0; nt < 7; nt++) {
                uint32_t bk0, bk1;
                unsigned addr = smem_u32(Ks + (nt * 8 + (lane & 7)) * ATT_LDS +
                                         kk * 16 + ((lane >> 3) & 1) * 8);
                asm volatile("ldmatrix.sync.aligned.m8n8.x2.shared.b16 {%0,%1}, [%2];\n"
                    : "=r"(bk0), "=r"(bk1) : "r"(addr));
                asm volatile(
                    "mma.sync.aligned.m16n8k16.row.col.f32.f16.f16.f32 "
                    "{%0,%1,%2,%3}, {%4,%5,%6,%7}, {%8,%9}, {%0,%1,%2,%3};\n"
                    : "+f"(sacc[nt][0]), "+f"(sacc[nt][1]),
                      "+f"(sacc[nt][2]), "+f"(sacc[nt][3])
                    : "r"(aq[kk][0]), "r"(aq[kk][1]), "r"(aq[kk][2]), "r"(aq[kk][3]),
                      "r"(bk0), "r"(bk1));
            }
        }

        const int q1 = mt * 16 + r1, q2 = q1 + 8;
        float mx1 = -1e30f, mx2 = -1e30f;
#pragma unroll
        for (int nt = 0; nt < 7; nt++) {
            float2 t1 = *(const float2*)&Trow[q1 * 56 + nt * 8 + cb];
            float2 t2 = *(const float2*)&Trow[q2 * 56 + nt * 8 + cb];
            sacc[nt][0] = sacc[nt][0] * SCALE + t1.x;
            sacc[nt][1] = sacc[nt][1] * SCALE + t1.y;
            sacc[nt][2] = sacc[nt][2] * SCALE + t2.x;
            sacc[nt][3] = sacc[nt][3] * SCALE + t2.y;
            mx1 = fmaxf(mx1, fmaxf(sacc[nt][0], sacc[nt][1]));
            mx2 = fmaxf(mx2, fmaxf(sacc[nt][2], sacc[nt][3]));
        }
        mx1 = fmaxf(mx1, __shfl_xor_sync(0xFFFFFFFFu, mx1, 1));
        mx1 = fmaxf(mx1, __shfl_xor_sync(0xFFFFFFFFu, mx1, 2));
        mx2 = fmaxf(mx2, __shfl_xor_sync(0xFFFFFFFFu, mx2, 1));
        mx2 = fmaxf(mx2, __shfl_xor_sync(0xFFFFFFFFu, mx2, 2));

        float sum1 = 0.f, sum2 = 0.f;
#pragma unroll
        for (int nt = 0; nt < 7; nt++) {
            sacc[nt][0] = __expf(sacc[nt][0] - mx1);
            sacc[nt][1] = __expf(sacc[nt][1] - mx1);
            sacc[nt][2] = __expf(sacc[nt][2] - mx2);
            sacc[nt][3] = __expf(sacc[nt][3] - mx2);
            sum1 += sacc[nt][0] + sacc[nt][1];
            sum2 += sacc[nt][2] + sacc[nt][3];
        }
        sum1 += __shfl_xor_sync(0xFFFFFFFFu, sum1, 1);
        sum1 += __shfl_xor_sync(0xFFFFFFFFu, sum1, 2);
        sum2 += __shfl_xor_sync(0xFFFFFFFFu, sum2, 1);
        sum2 += __shfl_xor_sync(0xFFFFFFFFu, sum2, 2);
        float inv1 = 1.0f / sum1, inv2 = 1.0f / sum2;

        uint32_t ph[7][2];
#pragma unroll
        for (int nt = 0; nt < 7; nt++) {
            __half2 lo = __floats2half2_rn(sacc[nt][0] * inv1, sacc[nt][1] * inv1);
            __half2 hi = __floats2half2_rn(sacc[nt][2] * inv2, sacc[nt][3] * inv2);
            ph[nt][0] = *(uint32_t*)&lo;
            ph[nt][1] = *(uint32_t*)&hi;
        }

        float oa[4][4];
#pragma unroll
        for (int ni = 0; ni < 4; ni++)
#pragma unroll
            for (int c = 0; c < 4; c++) oa[ni][c] = 0.f;

#pragma unroll
        for (int kt = 0; kt < 4; kt++) {
            uint32_t a0 = ph[2 * kt][0];
            uint32_t a1 = ph[2 * kt][1];
            uint32_t a2 = (2 * kt + 1 < 7) ? ph[2 * kt + 1][0] : 0u;
            uint32_t a3 = (2 * kt + 1 < 7) ? ph[2 * kt + 1][1] : 0u;
#pragma unroll
            for (int ni = 0; ni < 4; ni++) {
                uint32_t bv0, bv1;
                unsigned addr = smem_u32(Vs + (kt * 16 + (lane & 15)) * ATT_LDS + ni * 8);
                asm volatile("ldmatrix.sync.aligned.m8n8.x2.trans.shared.b16 {%0,%1}, [%2];\n"
                    : "=r"(bv0), "=r"(bv1) : "r"(addr));
                asm volatile(
                    "mma.sync.aligned.m16n8k16.row.col.f32.f16.f16.f32 "
                    "{%0,%1,%2,%3}, {%4,%5,%6,%7}, {%8,%9}, {%0,%1,%2,%3};\n"
                    : "+f"(oa[ni][0]), "+f"(oa[ni][1]), "+f"(oa[ni][2]), "+f"(oa[ni][3])
                    : "r"(a0), "r"(a1), "r"(a2), "r"(a3), "r"(bv0), "r"(bv1));
            }
        }

        if (q1 < NT) {
            __half* op = O + ((size_t)(w * NT + q1)) * DIM + h * HDIM;
#pragma unroll
            for (int ni = 0; ni < 4; ni++)
                *(__half2*)(op + ni * 8 + cb) = __floats2half2_rn(oa[ni][0], oa[ni][1]);
        }
        if (q2 < NT) {
            __half* op = O + ((size_t)(w * NT + q2)) * DIM + h * HDIM;
#pragma unroll
            for (int ni = 0; ni < 4; ni++)
                *(__half2*)(op + ni * 8 + cb) = __floats2half2_rn(oa[ni][2], oa[ni][3]);
        }
    }
}

// ---------------------------------------------------------------------------
// Launch
// ---------------------------------------------------------------------------
extern "C" void kernel_launch(void* const* d_in, const int* in_sizes, int n_in,
                              void* d_out, int out_size) {
    const float* x1     = (const float*)d_in[0];
    const float* x2     = (const float*)d_in[1];
    const float* amask  = (const float*)d_in[2];
    const float* g1     = (const float*)d_in[3];
    const float* be1    = (const float*)d_in[4];
    const float* w_qkv  = (const float*)d_in[5];
    const float* b_qkv  = (const float*)d_in[6];
    const float* rpb    = (const float*)d_in[7];
    const float* w_proj = (const float*)d_in[8];
    const float* b_proj = (const float*)d_in[9];
    const float* g2     = (const float*)d_in[10];
    const float* be2    = (const float*)d_in[11];
    const float* w_fc1  = (const float*)d_in[12];
    const float* b_fc1  = (const float*)d_in[13];
    const float* w_fc2  = (const float*)d_in[14];
    const float* b_fc2  = (const float*)d_in[15];

    float* out = (float*)d_out;
    float* y1 = out;
    float* y2 = out + (size_t)NTOK * DIM;

    void *pAwin, *pQ, *pK, *pV, *pO, *pA2, *pH, *pT;
    void *pWqkv, *pWproj, *pWfc1, *pWfc2;
    cudaGetSymbolAddress(&pAwin, g_Awin);
    cudaGetSymbolAddress(&pQ, g_Qh);
    cudaGetSymbolAddress(&pK, g_Kh);
    cudaGetSymbolAddress(&pV, g_Vh);
    cudaGetSymbolAddress(&pO, g_O);
    cudaGetSymbolAddress(&pA2, g_A2);
    cudaGetSymbolAddress(&pH, g_Hm);
    cudaGetSymbolAddress(&pT, g_T);
    cudaGetSymbolAddress(&pWqkv, g_Wqkv);
    cudaGetSymbolAddress(&pWproj, g_Wproj);
    cudaGetSymbolAddress(&pWfc1, g_Wfc1);
    cudaGetSymbolAddress(&pWfc2, g_Wfc2);

    cudaFuncSetAttribute(gemm_f16_kernel<EpiQKV>, cudaFuncAttributeMaxDynamicSharedMemorySize, GEMM_SMEM);
    cudaFuncSetAttribute(gemm_f16_kernel<EpiProj>, cudaFuncAttributeMaxDynamicSharedMemorySize, GEMM_SMEM);
    cudaFuncSetAttribute(gemm_f16_kernel<EpiGelu>, cudaFuncAttributeMaxDynamicSharedMemorySize, GEMM_SMEM);
    cudaFuncSetAttribute(gemm_f16_kernel<EpiY2>, cudaFuncAttributeMaxDynamicSharedMemorySize, GEMM_SMEM);

    // fused weight convert (1 launch)
    {
        int total = NQKV + NPRJ + NFC1 + NFC2;
        f2h_all_kernel<<<(total + 255) / 256, 256>>>(
            w_qkv, w_proj, w_fc1, w_fc2,
            (__half*)pWqkv, (__half*)pWproj, (__half*)pWfc1, (__half*)pWfc2);
    }

    build_table<<<(64 * 12 * 64 * 56 + 255) / 256, 256>>>(rpb, amask, (float*)pT);

    const int M = NTOK;

    ln_gather_kernel<<<NTOK / 4, 128>>>(x2, g1, be1, (__half*)pAwin);

    {
        EpiQKV e{b_qkv, (__half*)pQ, (__half*)pK, (__half*)pV};
        gemm_f16_kernel<EpiQKV><<<dim3(3 * DIM / 128, M / 128), 512, GEMM_SMEM>>>(
            (const __half*)pAwin, (const __half*)pWqkv, M, 3 * DIM, DIM, e);
    }

    attn_mma_kernel<<<NWIN * HEADS / 2, 64>>>((const __half*)pQ, (const __half*)pK,
                                              (const __half*)pV, (const float*)pT,
                                              (__half*)pO);

    {
        EpiProj e{b_proj, x1, y1};
        gemm_f16_kernel<EpiProj><<<dim3(DIM / 128, M / 128), 512, GEMM_SMEM>>>(
            (const __half*)pO, (const __half*)pWproj, M, DIM, DIM, e);
    }

    ln_plain_kernel<<<NTOK / 4, 128>>>(y1, g2, be2, (__half*)pA2);

    {
        EpiGelu e{b_fc1, (__half*)pH};
        gemm_f16_kernel<EpiGelu><<<dim3(4 * DIM / 128, M / 128), 512, GEMM_SMEM>>>(
            (const __half*)pA2, (const __half*)pWfc1, M, 4 * DIM, DIM, e);
    }

    {
        EpiY2 e{b_fc2, x2, y2};
        gemm_f16_kernel<EpiY2><<<dim3(DIM / 128, M / 128), 512, GEMM_SMEM>>>(
            (const __half*)pH, (const __half*)pWfc2, M, DIM, 4 * DIM, e);
    }
}

// round 14
// speedup vs baseline: 1.0127x; 1.0127x over previous
#include <cuda_runtime.h>
#include <cuda_fp16.h>
#include <cstdint>
#include <math.h>

// ---------------------------------------------------------------------------
// Problem constants
// ---------------------------------------------------------------------------
#define HIMG   56
#define WSZ    7
#define SSZ    3
#define DIM    384
#define HEADS  12
#define HDIM   32
#define NBATCH 16
#define NTOK   (NBATCH * HIMG * HIMG)     // 50176 rows
#define NWIMG  64
#define NWIN   (NBATCH * NWIMG)           // 1024 windows
#define NT     49                         // tokens per window

// ---------------------------------------------------------------------------
// Static scratch
// ---------------------------------------------------------------------------
__device__ __half g_Awin[(size_t)NTOK * DIM];
__device__ __half g_Qh[(size_t)NTOK * DIM];        // pre-scaled by 1/sqrt(d)
__device__ __half g_Kh[(size_t)NTOK * DIM];
__device__ __half g_Vh[(size_t)NTOK * DIM];
__device__ __half g_O[(size_t)NTOK * DIM];
__device__ __half g_A2[(size_t)NTOK * DIM];
__device__ __half g_Hm[(size_t)NTOK * 4 * DIM];
__device__ __half g_Wqkv[DIM * 3 * DIM];
__device__ __half g_Wproj[DIM * DIM];
__device__ __half g_Wfc1[DIM * 4 * DIM];
__device__ __half g_Wfc2[4 * DIM * DIM];
__device__ float  g_T[(size_t)64 * 12 * 64 * 56];

// ---------------------------------------------------------------------------
// fused fp32 -> fp16 weight conversion, vectorized (2 elems/thread)
// ---------------------------------------------------------------------------
#define NQKV (DIM * 3 * DIM)
#define NPRJ (DIM * DIM)
#define NFC1 (DIM * 4 * DIM)
#define NFC2 (4 * DIM * DIM)
__global__ void f2h_all_kernel(const float* __restrict__ s0, const float* __restrict__ s1,
                               const float* __restrict__ s2, const float* __restrict__ s3,
                               __half* __restrict__ d0, __half* __restrict__ d1,
                               __half* __restrict__ d2, __half* __restrict__ d3) {
    int i = (blockIdx.x * blockDim.x + threadIdx.x) * 2;   // all sizes even
    const float* s; __half* d;
    if (i < NQKV) { s = s0; d = d0; }
    else { i -= NQKV;
        if (i < NPRJ) { s = s1; d = d1; }
        else { i -= NPRJ;
            if (i < NFC1) { s = s2; d = d2; }
            else { i -= NFC1; if (i >= NFC2) return; s = s3; d = d3; }
        }
    }
    float2 v = *(const float2*)&s[i];
    *(__half2*)&d[i] = __floats2half2_rn(v.x, v.y);
}

// ---------------------------------------------------------------------------
// bias+mask table build: T[wi][h][q][c]
// ---------------------------------------------------------------------------
__global__ void build_table(const float* __restrict__ rpb, const float* __restrict__ mask,
                            float* __restrict__ T) {
    int t = blockIdx.x * 256 + threadIdx.x;
    const int total = 64 * 12 * 64 * 56;
    if (t >= total) return;
    int c = t % 56;
    int tmp = t / 56;
    int q = tmp & 63; tmp >>= 6;
    int h = tmp % 12;
    int wi = tmp / 12;
    float v;
    if (q < 49 && c < 49) {
        int i1 = q / 7, j1 = q - 7 * i1;
        int i2 = c / 7, j2 = c - 7 * i2;
        int ridx = (i1 - i2 + 6) * 13 + (j1 - j2 + 6);
        v = rpb[ridx * 12 + h] + mask[((size_t)wi * 49 + q) * 49 + c];
    } else {
        v = (q < 49) ? -1e30f : 0.f;
    }
    T[t] = v;
}

// ---------------------------------------------------------------------------
// LayerNorm kernels — vectorized: float2 loads, __half2 stores, 8 rows/block
// ---------------------------------------------------------------------------
__device__ __forceinline__ float warp_sum(float v) {
#pragma unroll
    for (int o = 16; o > 0; o >>= 1) v += __shfl_xor_sync(0xFFFFFFFFu, v, o);
    return v;
}

__global__ void ln_gather_kernel(const float* __restrict__ x, const float* __restrict__ g,
                                 const float* __restrict__ b, __half* __restrict__ out) {
    int r = blockIdx.x * 8 + (threadIdx.x >> 5);
    int lane = threadIdx.x & 31;
    int w = r / NT, n = r - w * NT;
    int bimg = w >> 6, wi = w & 63;
    int wr = wi >> 3, wc = wi & 7;
    int i = n / WSZ, j = n - i * WSZ;
    int hh = wr * WSZ + i + SSZ; if (hh >= HIMG) hh -= HIMG;
    int ww = wc * WSZ + j + SSZ; if (ww >= HIMG) ww -= HIMG;
    size_t t = (size_t)bimg * (HIMG * HIMG) + hh * HIMG + ww;
    const float* xp = x + t * DIM;

    float2 v[6];
    float s = 0.f;
#pragma unroll
    for (int k = 0; k < 6; k++) {
        v[k] = *(const float2*)&xp[2 * lane + 64 * k];
        s += v[k].x + v[k].y;
    }
    float mu = warp_sum(s) * (1.0f / DIM), s2 = 0.f;
#pragma unroll
    for (int k = 0; k < 6; k++) {
        float dx = v[k].x - mu, dy = v[k].y - mu;
        s2 += dx * dx + dy * dy;
    }
    float rs = rsqrtf(warp_sum(s2) * (1.0f / DIM) + 1e-5f);
    __half* op = out + (size_t)r * DIM;
#pragma unroll
    for (int k = 0; k < 6; k++) {
        int c = 2 * lane + 64 * k;
        float2 gg = *(const float2*)&g[c];
        float2 bb = *(const float2*)&b[c];
        *(__half2*)&op[c] = __floats2half2_rn((v[k].x - mu) * rs * gg.x + bb.x,
                                              (v[k].y - mu) * rs * gg.y + bb.y);
    }
}

__global__ void ln_plain_kernel(const float* __restrict__ x, const float* __restrict__ g,
                                const float* __restrict__ b, __half* __restrict__ out) {
    int r = blockIdx.x * 8 + (threadIdx.x >> 5);
    int lane = threadIdx.x & 31;
    const float* xp = x + (size_t)r * DIM;

    float2 v[6];
    float s = 0.f;
#pragma unroll
    for (int k = 0; k < 6; k++) {
        v[k] = *(const float2*)&xp[2 * lane + 64 * k];
        s += v[k].x + v[k].y;
    }
    float mu = warp_sum(s) * (1.0f / DIM), s2 = 0.f;
#pragma unroll
    for (int k = 0; k < 6; k++) {
        float dx = v[k].x - mu, dy = v[k].y - mu;
        s2 += dx * dx + dy * dy;
    }
    float rs = rsqrtf(warp_sum(s2) * (1.0f / DIM) + 1e-5f);
    __half* op = out + (size_t)r * DIM;
#pragma unroll
    for (int k = 0; k < 6; k++) {
        int c = 2 * lane + 64 * k;
        float2 gg = *(const float2*)&g[c];
        float2 bb = *(const float2*)&b[c];
        *(__half2*)&op[c] = __floats2half2_rn((v[k].x - mu) * rs * gg.x + bb.x,
                                              (v[k].y - mu) * rs * gg.y + bb.y);
    }
}

// ---------------------------------------------------------------------------
// fp16 GEMM (mma.sync m16n8k16): 128x128x64 CTA tile, 512 threads (16 warps),
// warp tile 32x32, 2-stage cp.async pipeline. (R13 config — at HMMA ceiling.)
// Epilogue consumes PAIRS: epi(r, c, v_c, v_{c+1}).
// ---------------------------------------------------------------------------
__device__ __forceinline__ unsigned smem_u32(const void* p) {
    return (unsigned)__cvta_generic_to_shared(p);
}

#define BKL       64
#define A_STRIDE  72
#define B_STRIDE  136
#define A_BYTES   (128 * A_STRIDE * 2)
#define STAGE_B   (A_BYTES + BKL * B_STRIDE * 2)
#define GEMM_SMEM (2 * STAGE_B)

template <class Epi>
__global__ void __launch_bounds__(512, 2)
gemm_f16_kernel(const __half* __restrict__ A, const __half* __restrict__ Bw,
                int M, int N, int K, Epi epi) {
    extern __shared__ char smem[];
    const uint32_t sb = smem_u32(smem);

    const int tid = threadIdx.x;
    const int warp = tid >> 5, lane = tid & 31;
    const int wm = (warp >> 2) * 32;
    const int wn = (warp & 3) * 32;
    const int bm = blockIdx.y * 128;
    const int bn = blockIdx.x * 128;

    const __half* Abase = A + (size_t)bm * K;
    const __half* Bbase = Bw + bn;

    auto load_stage = [&](int st, int k0) {
        uint32_t abase = sb + st * STAGE_B;
        uint32_t bbase = abase + A_BYTES;
#pragma unroll
        for (int j = 0; j < 2; j++) {
            int idx = tid + j * 512;
            int r = idx >> 3, c8 = (idx & 7) * 8;
            unsigned d = abase + (r * A_STRIDE + c8) * 2;
            const void* s = Abase + (size_t)r * K + k0 + c8;
            asm volatile("cp.async.cg.shared.global [%0], [%1], 16;\n" :: "r"(d), "l"(s));
        }
#pragma unroll
        for (int j = 0; j < 2; j++) {
            int idx = tid + j * 512;
            int r = idx >> 4, c8 = (idx & 15) * 8;
            unsigned d = bbase + (r * B_STRIDE + c8) * 2;
            const void* s = Bbase + (size_t)(k0 + r) * N + c8;
            asm volatile("cp.async.cg.shared.global [%0], [%1], 16;\n" :: "r"(d), "l"(s));
        }
    };

    float acc[2][4][4];
#pragma unroll
    for (int a = 0; a < 2; a++)
#pragma unroll
        for (int b = 0; b < 4; b++)
#pragma unroll
            for (int c = 0; c < 4; c++) acc[a][b][c] = 0.f;

    const int ktiles = K / BKL;

    load_stage(0, 0);
    asm volatile("cp.async.commit_group;\n");
    load_stage(1, BKL);
    asm volatile("cp.async.commit_group;\n");

    for (int i = 0; i < ktiles; i++) {
        asm volatile("cp.async.wait_group 1;\n");
        __syncthreads();

        const uint32_t abase = sb + (i & 1) * STAGE_B;
        const uint32_t bbase = abase + A_BYTES;

#pragma unroll
        for (int kk = 0; kk < BKL; kk += 16) {
            uint32_t af[2][4], bfx[2][4];
#pragma unroll
            for (int mi = 0; mi < 2; mi++) {
                unsigned addr = abase +
                    ((wm + mi * 16 + (lane & 15)) * A_STRIDE + kk + (lane >> 4) * 8) * 2;
                asm volatile(
                    "ldmatrix.sync.aligned.m8n8.x4.shared.b16 {%0,%1,%2,%3}, [%4];\n"
                    : "=r"(af[mi][0]), "=r"(af[mi][1]), "=r"(af[mi][2]), "=r"(af[mi][3])
                    : "r"(addr));
            }
#pragma unroll
            for (int g = 0; g < 2; g++) {
                unsigned addr = bbase +
                    ((kk + (lane & 15)) * B_STRIDE + wn + g * 16 + (lane >> 4) * 8) * 2;
                asm volatile(
                    "ldmatrix.sync.aligned.m8n8.x4.trans.shared.b16 {%0,%1,%2,%3}, [%4];\n"
                    : "=r"(bfx[g][0]), "=r"(bfx[g][1]), "=r"(bfx[g][2]), "=r"(bfx[g][3])
                    : "r"(addr));
            }
#pragma unroll
            for (int mi = 0; mi < 2; mi++)
#pragma unroll
                for (int ni = 0; ni < 4; ni++) {
                    const int g = ni >> 1, hhalf = (ni & 1) * 2;
                    asm volatile(
                        "mma.sync.aligned.m16n8k16.row.col.f32.f16.f16.f32 "
                        "{%0,%1,%2,%3}, {%4,%5,%6,%7}, {%8,%9}, {%0,%1,%2,%3};\n"
                        : "+f"(acc[mi][ni][0]), "+f"(acc[mi][ni][1]),
                          "+f"(acc[mi][ni][2]), "+f"(acc[mi][ni][3])
                        : "r"(af[mi][0]), "r"(af[mi][1]), "r"(af[mi][2]), "r"(af[mi][3]),
                          "r"(bfx[g][hhalf]), "r"(bfx[g][hhalf + 1]));
                }
        }
        __syncthreads();

        if (i + 2 < ktiles) load_stage(i & 1, (i + 2) * BKL);
        asm volatile("cp.async.commit_group;\n");
    }

    const int r0 = bm + wm + (lane >> 2);
    const int c0 = bn + wn + (lane & 3) * 2;
#pragma unroll
    for (int mi = 0; mi < 2; mi++) {
#pragma unroll
        for (int ni = 0; ni < 4; ni++) {
            int rr = r0 + mi * 16;
            int cc = c0 + ni * 8;
            epi(rr,     cc, acc[mi][ni][0], acc[mi][ni][1]);
            epi(rr + 8, cc, acc[mi][ni][2], acc[mi][ni][3]);
        }
    }
}

// ---------------------------------------------------------------------------
// Epilogue functors — pair interface (c, c+1)
// ---------------------------------------------------------------------------
struct EpiQKV {
    const float* bias;
    __half *Qo, *Ko, *Vo;
    __device__ __forceinline__ void operator()(int r, int c, float v0, float v1) const {
        v0 += bias[c]; v1 += bias[c + 1];
        int which = c / DIM;
        int rem = c - which * DIM;
        int h = rem >> 5, d = rem & 31;
        int w = r / NT, n = r - w * NT;
        size_t dst = (((size_t)(w * HEADS + h)) * NT + n) * HDIM + d;
        if (which == 0) {
            const float SC = 0.17677669529663687f;     // fold softmax scale into Q
            *(__half2*)&Qo[dst] = __floats2half2_rn(v0 * SC, v1 * SC);
        } else if (which == 1) {
            *(__half2*)&Ko[dst] = __floats2half2_rn(v0, v1);
        } else {
            *(__half2*)&Vo[dst] = __floats2half2_rn(v0, v1);
        }
    }
};

struct EpiProj {
    const float* bias;
    const float* x1;
    float* y1;
    __device__ __forceinline__ void operator()(int r, int c, float v0, float v1) const {
        int w = r / NT, n = r - w * NT;
        int bimg = w >> 6, wi = w & 63;
        int wr = wi >> 3, wc = wi & 7;
        int i = n / WSZ, j = n - i * WSZ;
        int hh = wr * WSZ + i + SSZ; if (hh >= HIMG) hh -= HIMG;
        int ww = wc * WSZ + j + SSZ; if (ww >= HIMG) ww -= HIMG;
        size_t t = (size_t)bimg * (HIMG * HIMG) + hh * HIMG + ww;
        size_t o = t * DIM + c;
        float2 xr = *(const float2*)&x1[o];
        float2 ov;
        ov.x = xr.x + v0 + bias[c];
        ov.y = xr.y + v1 + bias[c + 1];
        *(float2*)&y1[o] = ov;
    }
};

struct EpiGelu {
    const float* bias;
    __half* Ho;
    __device__ __forceinline__ void operator()(int r, int c, float v0, float v1) const {
        v0 += bias[c]; v1 += bias[c + 1];
        float g0 = 0.5f * v0 * (1.0f + erff(v0 * 0.70710678118654752f));
        float g1 = 0.5f * v1 * (1.0f + erff(v1 * 0.70710678118654752f));
        *(__half2*)&Ho[(size_t)r * (4 * DIM) + c] = __floats2half2_rn(g0, g1);
    }
};

struct EpiY2 {
    const float* bias;
    const float* x2;
    float* y2;
    __device__ __forceinline__ void operator()(int r, int c, float v0, float v1) const {
        size_t o = (size_t)r * DIM + c;
        float2 xr = *(const float2*)&x2[o];
        float2 ov;
        ov.x = xr.x + v0 + bias[c];
        ov.y = xr.y + v1 + bias[c + 1];
        *(float2*)&y2[o] = ov;
    }
};

// ---------------------------------------------------------------------------
// Tensor-core windowed attention (Q pre-scaled; table add only)
// ---------------------------------------------------------------------------
#define ATT_LDS 40

__global__ void __launch_bounds__(64)
attn_mma_kernel(const __half* __restrict__ Qg, const __half* __restrict__ Kg,
                const __half* __restrict__ Vg, const float* __restrict__ T,
                __half* __restrict__ O) {
    __shared__ __half sm[2][3][64 * ATT_LDS];

    const int warp = threadIdx.x >> 5, lane = threadIdx.x & 31;
    const int wh = blockIdx.x * 2 + warp;
    const int w = wh / HEADS, h = wh - w * HEADS;
    const int wi = w & 63;

    __half* Qs = sm[warp][0];
    __half* Ks = sm[warp][1];
    __half* Vs = sm[warp][2];

    const __half* gq = Qg + (size_t)wh * NT * HDIM;
    const __half* gk = Kg + (size_t)wh * NT * HDIM;
    const __half* gv = Vg + (size_t)wh * NT * HDIM;
    const uint4 zz = make_uint4(0u, 0u, 0u, 0u);
#pragma unroll
    for (int it = 0; it < 8; it++) {
        int idx = it * 32 + lane;
        int row = idx >> 2, ch = idx & 3;
        bool ok = row < NT;
        uint4 vq = ok ? *(const uint4*)(gq + (size_t)row * 32 + ch * 8) : zz;
        uint4 vk = ok ? *(const uint4*)(gk + (size_t)row * 32 + ch * 8) : zz;
        uint4 vv = ok ? *(const uint4*)(gv + (size_t)row * 32 + ch * 8) : zz;
        *(uint4*)(Qs + row * ATT_LDS + ch * 8) = vq;
        *(uint4*)(Ks + row * ATT_LDS + ch * 8) = vk;
        *(uint4*)(Vs + row * ATT_LDS + ch * 8) = vv;
    }
    __syncwarp();

    const float* Trow = T + (size_t)(wi * HEADS + h) * 64 * 56;
    const int r1 = lane >> 2;
    const int cb = (lane & 3) * 2;

#pragma unroll 1
    for (int mt = 0; mt < 4; mt++) {
        uint32_t aq[2][4];
#pragma unroll
        for (int kk = 0; kk < 2; kk++) {
            unsigned addr = smem_u32(Qs + (mt * 16 + (lane & 15)) * ATT_LDS +
                                     kk * 16 + (lane >> 4) * 8);
            asm volatile("ldmatrix.sync.aligned.m8n8.x4.shared.b16 {%0,%1,%2,%3}, [%4];\n"
                : "=r"(aq[kk][0]), "=r"(aq[kk][1]), "=r"(aq[kk][2]), "=r"(aq[kk][3])
                : "r"(addr));
        }

        float sacc[7][4];
#pragma unroll
        for (int nt = 0; nt < 7; nt++)
#pragma unroll
            for (int c = 0; c < 4; c++) sacc[nt][c] = 0.f;

#pragma unroll
        for (int kk = 0; kk < 2; kk++) {
#pragma unroll
            for (int nt = 0; nt < 7; nt++) {
                uint32_t bk0, bk1;
                unsigned addr = smem_u32(Ks + (nt * 8 + (lane & 7)) * ATT_LDS +
                                         kk * 16 + ((lane >> 3) & 1) * 8);
                asm volatile("ldmatrix.sync.aligned.m8n8.x2.shared.b16 {%0,%1}, [%2];\n"
                    : "=r"(bk0), "=r"(bk1) : "r"(addr));
                asm volatile(
                    "mma.sync.aligned.m16n8k16.row.col.f32.f16.f16.f32 "
                    "{%0,%1,%2,%3}, {%4,%5,%6,%7}, {%8,%9}, {%0,%1,%2,%3};\n"
                    : "+f"(sacc[nt][0]), "+f"(sacc[nt][1]),
                      "+f"(sacc[nt][2]), "+f"(sacc[nt][3])
                    : "r"(aq[kk][0]), "r"(aq[kk][1]), "r"(aq[kk][2]), "r"(aq[kk][3]),
                      "r"(bk0), "r"(bk1));
            }
        }

        const int q1 = mt * 16 + r1, q2 = q1 + 8;
        float mx1 = -1e30f, mx2 = -1e30f;
#pragma unroll
        for (int nt = 0; nt < 7; nt++) {
            float2 t1 = *(const float2*)&Trow[q1 * 56 + nt * 8 + cb];
            float2 t2 = *(const float2*)&Trow[q2 * 56 + nt * 8 + cb];
            sacc[nt][0] += t1.x;
            sacc[nt][1] += t1.y;
            sacc[nt][2] += t2.x;
            sacc[nt][3] += t2.y;
            mx1 = fmaxf(mx1, fmaxf(sacc[nt][0], sacc[nt][1]));
            mx2 = fmaxf(mx2, fmaxf(sacc[nt][2], sacc[nt][3]));
        }
        mx1 = fmaxf(mx1, __shfl_xor_sync(0xFFFFFFFFu, mx1, 1));
        mx1 = fmaxf(mx1, __shfl_xor_sync(0xFFFFFFFFu, mx1, 2));
        mx2 = fmaxf(mx2, __shfl_xor_sync(0xFFFFFFFFu, mx2, 1));
        mx2 = fmaxf(mx2, __shfl_xor_sync(0xFFFFFFFFu, mx2, 2));

        float sum1 = 0.f, sum2 = 0.f;
#pragma unroll
        for (int nt = 0; nt < 7; nt++) {
            sacc[nt][0] = __expf(sacc[nt][0] - mx1);
            sacc[nt][1] = __expf(sacc[nt][1] - mx1);
            sacc[nt][2] = __expf(sacc[nt][2] - mx2);
            sacc[nt][3] = __expf(sacc[nt][3] - mx2);
            sum1 += sacc[nt][0] + sacc[nt][1];
            sum2 += sacc[nt][2] + sacc[nt][3];
        }
        sum1 += __shfl_xor_sync(0xFFFFFFFFu, sum1, 1);
        sum1 += __shfl_xor_sync(0xFFFFFFFFu, sum1, 2);
        sum2 += __shfl_xor_sync(0xFFFFFFFFu, sum2, 1);
        sum2 += __shfl_xor_sync(0xFFFFFFFFu, sum2, 2);
        float inv1 = 1.0f / sum1, inv2 = 1.0f / sum2;

        uint32_t ph[7][2];
#pragma unroll
        for (int nt = 0; nt < 7; nt++) {
            __half2 lo = __floats2half2_rn(sacc[nt][0] * inv1, sacc[nt][1] * inv1);
            __half2 hi = __floats2half2_rn(sacc[nt][2] * inv2, sacc[nt][3] * inv2);
            ph[nt][0] = *(uint32_t*)&lo;
            ph[nt][1] = *(uint32_t*)&hi;
        }

        float oa[4][4];
#pragma unroll
        for (int ni = 0; ni < 4; ni++)
#pragma unroll
            for (int c = 0; c < 4; c++) oa[ni][c] = 0.f;

#pragma unroll
        for (int kt = 0; kt < 4; kt++) {
            uint32_t a0 = ph[2 * kt][0];
            uint32_t a1 = ph[2 * kt][1];
            uint32_t a2 = (2 * kt + 1 < 7) ? ph[2 * kt + 1][0] : 0u;
            uint32_t a3 = (2 * kt + 1 < 7) ? ph[2 * kt + 1][1] : 0u;
#pragma unroll
            for (int ni = 0; ni < 4; ni++) {
                uint32_t bv0, bv1;
                unsigned addr = smem_u32(Vs + (kt * 16 + (lane & 15)) * ATT_LDS + ni * 8);
                asm volatile("ldmatrix.sync.aligned.m8n8.x2.trans.shared.b16 {%0,%1}, [%2];\n"
                    : "=r"(bv0), "=r"(bv1) : "r"(addr));
                asm volatile(
                    "mma.sync.aligned.m16n8k16.row.col.f32.f16.f16.f32 "
                    "{%0,%1,%2,%3}, {%4,%5,%6,%7}, {%8,%9}, {%0,%1,%2,%3};\n"
                    : "+f"(oa[ni][0]), "+f"(oa[ni][1]), "+f"(oa[ni][2]), "+f"(oa[ni][3])
                    : "r"(a0), "r"(a1), "r"(a2), "r"(a3), "r"(bv0), "r"(bv1));
            }
        }

        if (q1 < NT) {
            __half* op = O + ((size_t)(w * NT + q1)) * DIM + h * HDIM;
#pragma unroll
            for (int ni = 0; ni < 4; ni++)
                *(__half2*)(op + ni * 8 + cb) = __floats2half2_rn(oa[ni][0], oa[ni][1]);
        }
        if (q2 < NT) {
            __half* op = O + ((size_t)(w * NT + q2)) * DIM + h * HDIM;
#pragma unroll
            for (int ni = 0; ni < 4; ni++)
                *(__half2*)(op + ni * 8 + cb) = __floats2half2_rn(oa[ni][2], oa[ni][3]);
        }
    }
}

// ---------------------------------------------------------------------------
// Launch
// ---------------------------------------------------------------------------
extern "C" void kernel_launch(void* const* d_in, const int* in_sizes, int n_in,
                              void* d_out, int out_size) {
    const float* x1     = (const float*)d_in[0];
    const float* x2     = (const float*)d_in[1];
    const float* amask  = (const float*)d_in[2];
    const float* g1     = (const float*)d_in[3];
    const float* be1    = (const float*)d_in[4];
    const float* w_qkv  = (const float*)d_in[5];
    const float* b_qkv  = (const float*)d_in[6];
    const float* rpb    = (const float*)d_in[7];
    const float* w_proj = (const float*)d_in[8];
    const float* b_proj = (const float*)d_in[9];
    const float* g2     = (const float*)d_in[10];
    const float* be2    = (const float*)d_in[11];
    const float* w_fc1  = (const float*)d_in[12];
    const float* b_fc1  = (const float*)d_in[13];
    const float* w_fc2  = (const float*)d_in[14];
    const float* b_fc2  = (const float*)d_in[15];

    float* out = (float*)d_out;
    float* y1 = out;
    float* y2 = out + (size_t)NTOK * DIM;

    void *pAwin, *pQ, *pK, *pV, *pO, *pA2, *pH, *pT;
    void *pWqkv, *pWproj, *pWfc1, *pWfc2;
    cudaGetSymbolAddress(&pAwin, g_Awin);
    cudaGetSymbolAddress(&pQ, g_Qh);
    cudaGetSymbolAddress(&pK, g_Kh);
    cudaGetSymbolAddress(&pV, g_Vh);
    cudaGetSymbolAddress(&pO, g_O);
    cudaGetSymbolAddress(&pA2, g_A2);
    cudaGetSymbolAddress(&pH, g_Hm);
    cudaGetSymbolAddress(&pT, g_T);
    cudaGetSymbolAddress(&pWqkv, g_Wqkv);
    cudaGetSymbolAddress(&pWproj, g_Wproj);
    cudaGetSymbolAddress(&pWfc1, g_Wfc1);
    cudaGetSymbolAddress(&pWfc2, g_Wfc2);

    cudaFuncSetAttribute(gemm_f16_kernel<EpiQKV>, cudaFuncAttributeMaxDynamicSharedMemorySize, GEMM_SMEM);
    cudaFuncSetAttribute(gemm_f16_kernel<EpiProj>, cudaFuncAttributeMaxDynamicSharedMemorySize, GEMM_SMEM);
    cudaFuncSetAttribute(gemm_f16_kernel<EpiGelu>, cudaFuncAttributeMaxDynamicSharedMemorySize, GEMM_SMEM);
    cudaFuncSetAttribute(gemm_f16_kernel<EpiY2>, cudaFuncAttributeMaxDynamicSharedMemorySize, GEMM_SMEM);

    {
        int total = (NQKV + NPRJ + NFC1 + NFC2) / 2;
        f2h_all_kernel<<<(total + 255) / 256, 256>>>(
            w_qkv, w_proj, w_fc1, w_fc2,
            (__half*)pWqkv, (__half*)pWproj, (__half*)pWfc1, (__half*)pWfc2);
    }

    build_table<<<(64 * 12 * 64 * 56 + 255) / 256, 256>>>(rpb, amask, (float*)pT);

    const int M = NTOK;

    ln_gather_kernel<<<NTOK / 8, 256>>>(x2, g1, be1, (__half*)pAwin);

    {
        EpiQKV e{b_qkv, (__half*)pQ, (__half*)pK, (__half*)pV};
        gemm_f16_kernel<EpiQKV><<<dim3(3 * DIM / 128, M / 128), 512, GEMM_SMEM>>>(
            (const __half*)pAwin, (const __half*)pWqkv, M, 3 * DIM, DIM, e);
    }

    attn_mma_kernel<<<NWIN * HEADS / 2, 64>>>((const __half*)pQ, (const __half*)pK,
                                              (const __half*)pV, (const float*)pT,
                                              (__half*)pO);

    {
        EpiProj e{b_proj, x1, y1};
        gemm_f16_kernel<EpiProj><<<dim3(DIM / 128, M / 128), 512, GEMM_SMEM>>>(
            (const __half*)pO, (const __half*)pWproj, M, DIM, DIM, e);
    }

    ln_plain_kernel<<<NTOK / 8, 256>>>(y1, g2, be2, (__half*)pA2);

    {
        EpiGelu e{b_fc1, (__half*)pH};
        gemm_f16_kernel<EpiGelu><<<dim3(4 * DIM / 128, M / 128), 512, GEMM_SMEM>>>(
            (const __half*)pA2, (const __half*)pWfc1, M, 4 * DIM, DIM, e);
    }

    {
        EpiY2 e{b_fc2, x2, y2};
        gemm_f16_kernel<EpiY2><<<dim3(DIM / 128, M / 128), 512, GEMM_SMEM>>>(
            (const __half*)pH, (const __half*)pWfc2, M, DIM, 4 * DIM, e);
    }
}

// round 15
// speedup vs baseline: 1.0262x; 1.0132x over previous
#include <cuda_runtime.h>
#include <cuda_fp16.h>
#include <cstdint>
#include <math.h>

// ---------------------------------------------------------------------------
// Problem constants
// ---------------------------------------------------------------------------
#define HIMG   56
#define WSZ    7
#define SSZ    3
#define DIM    384
#define HEADS  12
#define HDIM   32
#define NBATCH 16
#define NTOK   (NBATCH * HIMG * HIMG)     // 50176 rows
#define NWIMG  64
#define NWIN   (NBATCH * NWIMG)           // 1024 windows
#define NT     49                         // tokens per window
#define LOG2E  1.4426950408889634f

// ---------------------------------------------------------------------------
// Static scratch
// ---------------------------------------------------------------------------
__device__ __half g_Awin[(size_t)NTOK * DIM];
__device__ __half g_Qh[(size_t)NTOK * DIM];        // pre-scaled by log2e/sqrt(d)
__device__ __half g_Kh[(size_t)NTOK * DIM];
__device__ __half g_Vh[(size_t)NTOK * DIM];
__device__ __half g_O[(size_t)NTOK * DIM];
__device__ __half g_A2[(size_t)NTOK * DIM];
__device__ __half g_Hm[(size_t)NTOK * 4 * DIM];
__device__ __half g_Wqkv[DIM * 3 * DIM];
__device__ __half g_Wproj[DIM * DIM];
__device__ __half g_Wfc1[DIM * 4 * DIM];
__device__ __half g_Wfc2[4 * DIM * DIM];
__device__ __half g_T[(size_t)64 * 12 * 64 * 56];  // (rpb+mask)*log2e, fp16

// ---------------------------------------------------------------------------
// Fused prep kernel: LN1+shift+gather  |  weight f2h  |  bias/mask table.
// All three independent; one launch, branch by blockIdx range. 256 thr/block.
// ---------------------------------------------------------------------------
#define NQKV (DIM * 3 * DIM)
#define NPRJ (DIM * DIM)
#define NFC1 (DIM * 4 * DIM)
#define NFC2 (4 * DIM * DIM)
#define LN_BLOCKS   (NTOK / 8)                               // 6272
#define F2H_PAIRS   ((NQKV + NPRJ + NFC1 + NFC2) / 2)        // 884736
#define F2H_BLOCKS  (F2H_PAIRS / 256)                        // 3456
#define TBL_PAIRS   (64 * 12 * 64 * 28)                      // 1376256
#define TBL_BLOCKS  (TBL_PAIRS / 256)                        // 5376
#define PREP_BLOCKS (LN_BLOCKS + F2H_BLOCKS + TBL_BLOCKS)    // 15104

__device__ __forceinline__ float warp_sum(float v) {
#pragma unroll
    for (int o = 16; o > 0; o >>= 1) v += __shfl_xor_sync(0xFFFFFFFFu, v, o);
    return v;
}

__global__ void prep_kernel(const float* __restrict__ x2, const float* __restrict__ g1,
                            const float* __restrict__ be1, __half* __restrict__ Awin,
                            const float* __restrict__ w0, const float* __restrict__ w1,
                            const float* __restrict__ w2, const float* __restrict__ w3,
                            __half* __restrict__ d0, __half* __restrict__ d1,
                            __half* __restrict__ d2, __half* __restrict__ d3,
                            const float* __restrict__ rpb, const float* __restrict__ mask,
                            __half* __restrict__ T) {
    const int bid = blockIdx.x;
    if (bid < LN_BLOCKS) {
        // ---- LN1 + cyclic shift + window partition (warp per row) ----
        int r = bid * 8 + (threadIdx.x >> 5);
        int lane = threadIdx.x & 31;
        int w = r / NT, n = r - w * NT;
        int bimg = w >> 6, wi = w & 63;
        int wr = wi >> 3, wc = wi & 7;
        int i = n / WSZ, j = n - i * WSZ;
        int hh = wr * WSZ + i + SSZ; if (hh >= HIMG) hh -= HIMG;
        int ww = wc * WSZ + j + SSZ; if (ww >= HIMG) ww -= HIMG;
        size_t t = (size_t)bimg * (HIMG * HIMG) + hh * HIMG + ww;
        const float* xp = x2 + t * DIM;

        float2 v[6];
        float s = 0.f;
#pragma unroll
        for (int k = 0; k < 6; k++) {
            v[k] = *(const float2*)&xp[2 * lane + 64 * k];
            s += v[k].x + v[k].y;
        }
        float mu = warp_sum(s) * (1.0f / DIM), s2 = 0.f;
#pragma unroll
        for (int k = 0; k < 6; k++) {
            float dx = v[k].x - mu, dy = v[k].y - mu;
            s2 += dx * dx + dy * dy;
        }
        float rs = rsqrtf(warp_sum(s2) * (1.0f / DIM) + 1e-5f);
        __half* op = Awin + (size_t)r * DIM;
#pragma unroll
        for (int k = 0; k < 6; k++) {
            int c = 2 * lane + 64 * k;
            float2 gg = *(const float2*)&g1[c];
            float2 bb = *(const float2*)&be1[c];
            *(__half2*)&op[c] = __floats2half2_rn((v[k].x - mu) * rs * gg.x + bb.x,
                                                  (v[k].y - mu) * rs * gg.y + bb.y);
        }
    } else if (bid < LN_BLOCKS + F2H_BLOCKS) {
        // ---- weights fp32 -> fp16, 2 elems/thread ----
        int i = ((bid - LN_BLOCKS) * 256 + threadIdx.x) * 2;
        const float* s; __half* d;
        if (i < NQKV) { s = w0; d = d0; }
        else { i -= NQKV;
            if (i < NPRJ) { s = w1; d = d1; }
            else { i -= NPRJ;
                if (i < NFC1) { s = w2; d = d2; }
                else { i -= NFC1; s = w3; d = d3; }
            }
        }
        float2 v = *(const float2*)&s[i];
        *(__half2*)&d[i] = __floats2half2_rn(v.x, v.y);
    } else {
        // ---- (rpb + mask)*log2e table, fp16, pad = -60000 ----
        int t = (bid - LN_BLOCKS - F2H_BLOCKS) * 256 + threadIdx.x;  // pair index
        int c2 = t % 28;
        int tmp = t / 28;
        int q = tmp & 63; tmp >>= 6;
        int h = tmp % 12;
        int wi = tmp / 12;
        float vv[2];
#pragma unroll
        for (int u = 0; u < 2; u++) {
            int c = 2 * c2 + u;
            if (q < 49 && c < 49) {
                int i1 = q / 7, j1 = q - 7 * i1;
                int i2 = c / 7, j2 = c - 7 * i2;
                int ridx = (i1 - i2 + 6) * 13 + (j1 - j2 + 6);
                vv[u] = (rpb[ridx * 12 + h] + mask[((size_t)wi * 49 + q) * 49 + c]) * LOG2E;
            } else {
                vv[u] = (q < 49) ? -60000.f : 0.f;
            }
        }
        *(__half2*)&T[(size_t)t * 2] = __floats2half2_rn(vv[0], vv[1]);
    }
}

// ---------------------------------------------------------------------------
// LN2 (plain, vectorized)
// ---------------------------------------------------------------------------
__global__ void ln_plain_kernel(const float* __restrict__ x, const float* __restrict__ g,
                                const float* __restrict__ b, __half* __restrict__ out) {
    int r = blockIdx.x * 8 + (threadIdx.x >> 5);
    int lane = threadIdx.x & 31;
    const float* xp = x + (size_t)r * DIM;

    float2 v[6];
    float s = 0.f;
#pragma unroll
    for (int k = 0; k < 6; k++) {
        v[k] = *(const float2*)&xp[2 * lane + 64 * k];
        s += v[k].x + v[k].y;
    }
    float mu = warp_sum(s) * (1.0f / DIM), s2 = 0.f;
#pragma unroll
    for (int k = 0; k < 6; k++) {
        float dx = v[k].x - mu, dy = v[k].y - mu;
        s2 += dx * dx + dy * dy;
    }
    float rs = rsqrtf(warp_sum(s2) * (1.0f / DIM) + 1e-5f);
    __half* op = out + (size_t)r * DIM;
#pragma unroll
    for (int k = 0; k < 6; k++) {
        int c = 2 * lane + 64 * k;
        float2 gg = *(const float2*)&g[c];
        float2 bb = *(const float2*)&b[c];
        *(__half2*)&op[c] = __floats2half2_rn((v[k].x - mu) * rs * gg.x + bb.x,
                                              (v[k].y - mu) * rs * gg.y + bb.y);
    }
}

// ---------------------------------------------------------------------------
// fp16 GEMM (mma.sync m16n8k16): 128x128x64 CTA tile, 512 threads (16 warps),
// warp tile 32x32, 2-stage cp.async pipeline. (R13/R14 config — at HMMA ceiling.)
// Epilogue consumes PAIRS: epi(r, c, v_c, v_{c+1}).
// ---------------------------------------------------------------------------
__device__ __forceinline__ unsigned smem_u32(const void* p) {
    return (unsigned)__cvta_generic_to_shared(p);
}

#define BKL       64
#define A_STRIDE  72
#define B_STRIDE  136
#define A_BYTES   (128 * A_STRIDE * 2)
#define STAGE_B   (A_BYTES + BKL * B_STRIDE * 2)
#define GEMM_SMEM (2 * STAGE_B)

template <class Epi>
__global__ void __launch_bounds__(512, 2)
gemm_f16_kernel(const __half* __restrict__ A, const __half* __restrict__ Bw,
                int M, int N, int K, Epi epi) {
    extern __shared__ char smem[];
    const uint32_t sb = smem_u32(smem);

    const int tid = threadIdx.x;
    const int warp = tid >> 5, lane = tid & 31;
    const int wm = (warp >> 2) * 32;
    const int wn = (warp & 3) * 32;
    const int bm = blockIdx.y * 128;
    const int bn = blockIdx.x * 128;

    const __half* Abase = A + (size_t)bm * K;
    const __half* Bbase = Bw + bn;

    auto load_stage = [&](int st, int k0) {
        uint32_t abase = sb + st * STAGE_B;
        uint32_t bbase = abase + A_BYTES;
#pragma unroll
        for (int j = 0; j < 2; j++) {
            int idx = tid + j * 512;
            int r = idx >> 3, c8 = (idx & 7) * 8;
            unsigned d = abase + (r * A_STRIDE + c8) * 2;
            const void* s = Abase + (size_t)r * K + k0 + c8;
            asm volatile("cp.async.cg.shared.global [%0], [%1], 16;\n" :: "r"(d), "l"(s));
        }
#pragma unroll
        for (int j = 0; j < 2; j++) {
            int idx = tid + j * 512;
            int r = idx >> 4, c8 = (idx & 15) * 8;
            unsigned d = bbase + (r * B_STRIDE + c8) * 2;
            const void* s = Bbase + (size_t)(k0 + r) * N + c8;
            asm volatile("cp.async.cg.shared.global [%0], [%1], 16;\n" :: "r"(d), "l"(s));
        }
    };

    float acc[2][4][4];
#pragma unroll
    for (int a = 0; a < 2; a++)
#pragma unroll
        for (int b = 0; b < 4; b++)
#pragma unroll
            for (int c = 0; c < 4; c++) acc[a][b][c] = 0.f;

    const int ktiles = K / BKL;

    load_stage(0, 0);
    asm volatile("cp.async.commit_group;\n");
    load_stage(1, BKL);
    asm volatile("cp.async.commit_group;\n");

    for (int i = 0; i < ktiles; i++) {
        asm volatile("cp.async.wait_group 1;\n");
        __syncthreads();

        const uint32_t abase = sb + (i & 1) * STAGE_B;
        const uint32_t bbase = abase + A_BYTES;

#pragma unroll
        for (int kk = 0; kk < BKL; kk += 16) {
            uint32_t af[2][4], bfx[2][4];
#pragma unroll
            for (int mi = 0; mi < 2; mi++) {
                unsigned addr = abase +
                    ((wm + mi * 16 + (lane & 15)) * A_STRIDE + kk + (lane >> 4) * 8) * 2;
                asm volatile(
                    "ldmatrix.sync.aligned.m8n8.x4.shared.b16 {%0,%1,%2,%3}, [%4];\n"
                    : "=r"(af[mi][0]), "=r"(af[mi][1]), "=r"(af[mi][2]), "=r"(af[mi][3])
                    : "r"(addr));
            }
#pragma unroll
            for (int g = 0; g < 2; g++) {
                unsigned addr = bbase +
                    ((kk + (lane & 15)) * B_STRIDE + wn + g * 16 + (lane >> 4) * 8) * 2;
                asm volatile(
                    "ldmatrix.sync.aligned.m8n8.x4.trans.shared.b16 {%0,%1,%2,%3}, [%4];\n"
                    : "=r"(bfx[g][0]), "=r"(bfx[g][1]), "=r"(bfx[g][2]), "=r"(bfx[g][3])
                    : "r"(addr));
            }
#pragma unroll
            for (int mi = 0; mi < 2; mi++)
#pragma unroll
                for (int ni = 0; ni < 4; ni++) {
                    const int g = ni >> 1, hhalf = (ni & 1) * 2;
                    asm volatile(
                        "mma.sync.aligned.m16n8k16.row.col.f32.f16.f16.f32 "
                        "{%0,%1,%2,%3}, {%4,%5,%6,%7}, {%8,%9}, {%0,%1,%2,%3};\n"
                        : "+f"(acc[mi][ni][0]), "+f"(acc[mi][ni][1]),
                          "+f"(acc[mi][ni][2]), "+f"(acc[mi][ni][3])
                        : "r"(af[mi][0]), "r"(af[mi][1]), "r"(af[mi][2]), "r"(af[mi][3]),
                          "r"(bfx[g][hhalf]), "r"(bfx[g][hhalf + 1]));
                }
        }
        __syncthreads();

        if (i + 2 < ktiles) load_stage(i & 1, (i + 2) * BKL);
        asm volatile("cp.async.commit_group;\n");
    }

    const int r0 = bm + wm + (lane >> 2);
    const int c0 = bn + wn + (lane & 3) * 2;
#pragma unroll
    for (int mi = 0; mi < 2; mi++) {
#pragma unroll
        for (int ni = 0; ni < 4; ni++) {
            int rr = r0 + mi * 16;
            int cc = c0 + ni * 8;
            epi(rr,     cc, acc[mi][ni][0], acc[mi][ni][1]);
            epi(rr + 8, cc, acc[mi][ni][2], acc[mi][ni][3]);
        }
    }
}

// ---------------------------------------------------------------------------
// Epilogue functors — pair interface (c, c+1)
// ---------------------------------------------------------------------------
struct EpiQKV {
    const float* bias;
    __half *Qo, *Ko, *Vo;
    __device__ __forceinline__ void operator()(int r, int c, float v0, float v1) const {
        v0 += bias[c]; v1 += bias[c + 1];
        int which = c / DIM;
        int rem = c - which * DIM;
        int h = rem >> 5, d = rem & 31;
        int w = r / NT, n = r - w * NT;
        size_t dst = (((size_t)(w * HEADS + h)) * NT + n) * HDIM + d;
        if (which == 0) {
            const float SC = 0.17677669529663687f * LOG2E;  // softmax scale * log2e
            *(__half2*)&Qo[dst] = __floats2half2_rn(v0 * SC, v1 * SC);
        } else if (which == 1) {
            *(__half2*)&Ko[dst] = __floats2half2_rn(v0, v1);
        } else {
            *(__half2*)&Vo[dst] = __floats2half2_rn(v0, v1);
        }
    }
};

struct EpiProj {
    const float* bias;
    const float* x1;
    float* y1;
    __device__ __forceinline__ void operator()(int r, int c, float v0, float v1) const {
        int w = r / NT, n = r - w * NT;
        int bimg = w >> 6, wi = w & 63;
        int wr = wi >> 3, wc = wi & 7;
        int i = n / WSZ, j = n - i * WSZ;
        int hh = wr * WSZ + i + SSZ; if (hh >= HIMG) hh -= HIMG;
        int ww = wc * WSZ + j + SSZ; if (ww >= HIMG) ww -= HIMG;
        size_t t = (size_t)bimg * (HIMG * HIMG) + hh * HIMG + ww;
        size_t o = t * DIM + c;
        float2 xr = *(const float2*)&x1[o];
        float2 ov;
        ov.x = xr.x + v0 + bias[c];
        ov.y = xr.y + v1 + bias[c + 1];
        *(float2*)&y1[o] = ov;
    }
};

struct EpiGelu {
    const float* bias;
    __half* Ho;
    __device__ __forceinline__ void operator()(int r, int c, float v0, float v1) const {
        v0 += bias[c]; v1 += bias[c + 1];
        float g0 = 0.5f * v0 * (1.0f + erff(v0 * 0.70710678118654752f));
        float g1 = 0.5f * v1 * (1.0f + erff(v1 * 0.70710678118654752f));
        *(__half2*)&Ho[(size_t)r * (4 * DIM) + c] = __floats2half2_rn(g0, g1);
    }
};

struct EpiY2 {
    const float* bias;
    const float* x2;
    float* y2;
    __device__ __forceinline__ void operator()(int r, int c, float v0, float v1) const {
        size_t o = (size_t)r * DIM + c;
        float2 xr = *(const float2*)&x2[o];
        float2 ov;
        ov.x = xr.x + v0 + bias[c];
        ov.y = xr.y + v1 + bias[c + 1];
        *(float2*)&y2[o] = ov;
    }
};

// ---------------------------------------------------------------------------
// Tensor-core windowed attention (Q pre-scaled incl. log2e; T fp16; exp2)
// ---------------------------------------------------------------------------
#define ATT_LDS 40

__global__ void __launch_bounds__(64)
attn_mma_kernel(const __half* __restrict__ Qg, const __half* __restrict__ Kg,
                const __half* __restrict__ Vg, const __half* __restrict__ T,
                __half* __restrict__ O) {
    __shared__ __half sm[2][3][64 * ATT_LDS];

    const int warp = threadIdx.x >> 5, lane = threadIdx.x & 31;
    const int wh = blockIdx.x * 2 + warp;
    const int w = wh / HEADS, h = wh - w * HEADS;
    const int wi = w & 63;

    __half* Qs = sm[warp][0];
    __half* Ks = sm[warp][1];
    __half* Vs = sm[warp][2];

    const __half* gq = Qg + (size_t)wh * NT * HDIM;
    const __half* gk = Kg + (size_t)wh * NT * HDIM;
    const __half* gv = Vg + (size_t)wh * NT * HDIM;
    const uint4 zz = make_uint4(0u, 0u, 0u, 0u);
#pragma unroll
    for (int it = 0; it < 8; it++) {
        int idx = it * 32 + lane;
        int row = idx >> 2, ch = idx & 3;
        bool ok = row < NT;
        uint4 vq = ok ? *(const uint4*)(gq + (size_t)row * 32 + ch * 8) : zz;
        uint4 vk = ok ? *(const uint4*)(gk + (size_t)row * 32 + ch * 8) : zz;
        uint4 vv = ok ? *(const uint4*)(gv + (size_t)row * 32 + ch * 8) : zz;
        *(uint4*)(Qs + row * ATT_LDS + ch * 8) = vq;
        *(uint4*)(Ks + row * ATT_LDS + ch * 8) = vk;
        *(uint4*)(Vs + row * ATT_LDS + ch * 8) = vv;
    }
    __syncwarp();

    const __half* Trow = T + (size_t)(wi * HEADS + h) * 64 * 56;
    const int r1 = lane >> 2;
    const int cb = (lane & 3) * 2;

#pragma unroll 1
    for (int mt = 0; mt < 4; mt++) {
        uint32_t aq[2][4];
#pragma unroll
        for (int kk = 0; kk < 2; kk++) {
            unsigned addr = smem_u32(Qs + (mt * 16 + (lane & 15)) * ATT_LDS +
                                     kk * 16 + (lane >> 4) * 8);
            asm volatile("ldmatrix.sync.aligned.m8n8.x4.shared.b16 {%0,%1,%2,%3}, [%4];\n"
                : "=r"(aq[kk][0]), "=r"(aq[kk][1]), "=r"(aq[kk][2]), "=r"(aq[kk][3])
                : "r"(addr));
        }

        float sacc[7][4];
#pragma unroll
        for (int nt = 0; nt < 7; nt++)
#pragma unroll
            for (int c = 0; c < 4; c++) sacc[nt][c] = 0.f;

#pragma unroll
        for (int kk = 0; kk < 2; kk++) {
#pragma unroll
            for (int nt = 0; nt < 7; nt++) {
                uint32_t bk0, bk1;
                unsigned addr = smem_u32(Ks + (nt * 8 + (lane & 7)) * ATT_LDS +
                                         kk * 16 + ((lane >> 3) & 1) * 8);
                asm volatile("ldmatrix.sync.aligned.m8n8.x2.shared.b16 {%0,%1}, [%2];\n"
                    : "=r"(bk0), "=r"(bk1) : "r"(addr));
                asm volatile(
                    "mma.sync.aligned.m16n8k16.row.col.f32.f16.f16.f32 "
                    "{%0,%1,%2,%3}, {%4,%5,%6,%7}, {%8,%9}, {%0,%1,%2,%3};\n"
                    : "+f"(sacc[nt][0]), "+f"(sacc[nt][1]),
                      "+f"(sacc[nt][2]), "+f"(sacc[nt][3])
                    : "r"(aq[kk][0]), "r"(aq[kk][1]), "r"(aq[kk][2]), "r"(aq[kk][3]),
                      "r"(bk0), "r"(bk1));
            }
        }

        const int q1 = mt * 16 + r1, q2 = q1 + 8;
        float mx1 = -1e30f, mx2 = -1e30f;
#pragma unroll
        for (int nt = 0; nt < 7; nt++) {
            float2 t1 = __half22float2(*(const __half2*)&Trow[q1 * 56 + nt * 8 + cb]);
            float2 t2 = __half22float2(*(const __half2*)&Trow[q2 * 56 + nt * 8 + cb]);
            sacc[nt][0] += t1.x;
            sacc[nt][1] += t1.y;
            sacc[nt][2] += t2.x;
            sacc[nt][3] += t2.y;
            mx1 = fmaxf(mx1, fmaxf(sacc[nt][0], sacc[nt][1]));
            mx2 = fmaxf(mx2, fmaxf(sacc[nt][2], sacc[nt][3]));
        }
        mx1 = fmaxf(mx1, __shfl_xor_sync(0xFFFFFFFFu, mx1, 1));
        mx1 = fmaxf(mx1, __shfl_xor_sync(0xFFFFFFFFu, mx1, 2));
        mx2 = fmaxf(mx2, __shfl_xor_sync(0xFFFFFFFFu, mx2, 1));
        mx2 = fmaxf(mx2, __shfl_xor_sync(0xFFFFFFFFu, mx2, 2));

        float sum1 = 0.f, sum2 = 0.f;
#pragma unroll
        for (int nt = 0; nt < 7; nt++) {
            sacc[nt][0] = exp2f(sacc[nt][0] - mx1);
            sacc[nt][1] = exp2f(sacc[nt][1] - mx1);
            sacc[nt][2] = exp2f(sacc[nt][2] - mx2);
            sacc[nt][3] = exp2f(sacc[nt][3] - mx2);
            sum1 += sacc[nt][0] + sacc[nt][1];
            sum2 += sacc[nt][2] + sacc[nt][3];
        }
        sum1 += __shfl_xor_sync(0xFFFFFFFFu, sum1, 1);
        sum1 += __shfl_xor_sync(0xFFFFFFFFu, sum1, 2);
        sum2 += __shfl_xor_sync(0xFFFFFFFFu, sum2, 1);
        sum2 += __shfl_xor_sync(0xFFFFFFFFu, sum2, 2);
        float inv1 = 1.0f / sum1, inv2 = 1.0f / sum2;

        uint32_t ph[7][2];
#pragma unroll
        for (int nt = 0; nt < 7; nt++) {
            __half2 lo = __floats2half2_rn(sacc[nt][0] * inv1, sacc[nt][1] * inv1);
            __half2 hi = __floats2half2_rn(sacc[nt][2] * inv2, sacc[nt][3] * inv2);
            ph[nt][0] = *(uint32_t*)&lo;
            ph[nt][1] = *(uint32_t*)&hi;
        }

        float oa[4][4];
#pragma unroll
        for (int ni = 0; ni < 4; ni++)
#pragma unroll
            for (int c = 0; c < 4; c++) oa[ni][c] = 0.f;

#pragma unroll
        for (int kt = 0; kt < 4; kt++) {
            uint32_t a0 = ph[2 * kt][0];
            uint32_t a1 = ph[2 * kt][1];
            uint32_t a2 = (2 * kt + 1 < 7) ? ph[2 * kt + 1][0] : 0u;
            uint32_t a3 = (2 * kt + 1 < 7) ? ph[2 * kt + 1][1] : 0u;
#pragma unroll
            for (int ni = 0; ni < 4; ni++) {
                uint32_t bv0, bv1;
                unsigned addr = smem_u32(Vs + (kt * 16 + (lane & 15)) * ATT_LDS + ni * 8);
                asm volatile("ldmatrix.sync.aligned.m8n8.x2.trans.shared.b16 {%0,%1}, [%2];\n"
                    : "=r"(bv0), "=r"(bv1) : "r"(addr));
                asm volatile(
                    "mma.sync.aligned.m16n8k16.row.col.f32.f16.f16.f32 "
                    "{%0,%1,%2,%3}, {%4,%5,%6,%7}, {%8,%9}, {%0,%1,%2,%3};\n"
                    : "+f"(oa[ni][0]), "+f"(oa[ni][1]), "+f"(oa[ni][2]), "+f"(oa[ni][3])
                    : "r"(a0), "r"(a1), "r"(a2), "r"(a3), "r"(bv0), "r"(bv1));
            }
        }

        if (q1 < NT) {
            __half* op = O + ((size_t)(w * NT + q1)) * DIM + h * HDIM;
#pragma unroll
            for (int ni = 0; ni < 4; ni++)
                *(__half2*)(op + ni * 8 + cb) = __floats2half2_rn(oa[ni][0], oa[ni][1]);
        }
        if (q2 < NT) {
            __half* op = O + ((size_t)(w * NT + q2)) * DIM + h * HDIM;
#pragma unroll
            for (int ni = 0; ni < 4; ni++)
                *(__half2*)(op + ni * 8 + cb) = __floats2half2_rn(oa[ni][2], oa[ni][3]);
        }
    }
}

// ---------------------------------------------------------------------------
// Launch
// ---------------------------------------------------------------------------
extern "C" void kernel_launch(void* const* d_in, const int* in_sizes, int n_in,
                              void* d_out, int out_size) {
    const float* x1     = (const float*)d_in[0];
    const float* x2     = (const float*)d_in[1];
    const float* amask  = (const float*)d_in[2];
    const float* g1     = (const float*)d_in[3];
    const float* be1    = (const float*)d_in[4];
    const float* w_qkv  = (const float*)d_in[5];
    const float* b_qkv  = (const float*)d_in[6];
    const float* rpb    = (const float*)d_in[7];
    const float* w_proj = (const float*)d_in[8];
    const float* b_proj = (const float*)d_in[9];
    const float* g2     = (const float*)d_in[10];
    const float* be2    = (const float*)d_in[11];
    const float* w_fc1  = (const float*)d_in[12];
    const float* b_fc1  = (const float*)d_in[13];
    const float* w_fc2  = (const float*)d_in[14];
    const float* b_fc2  = (const float*)d_in[15];

    float* out = (float*)d_out;
    float* y1 = out;
    float* y2 = out + (size_t)NTOK * DIM;

    void *pAwin, *pQ, *pK, *pV, *pO, *pA2, *pH, *pT;
    void *pWqkv, *pWproj, *pWfc1, *pWfc2;
    cudaGetSymbolAddress(&pAwin, g_Awin);
    cudaGetSymbolAddress(&pQ, g_Qh);
    cudaGetSymbolAddress(&pK, g_Kh);
    cudaGetSymbolAddress(&pV, g_Vh);
    cudaGetSymbolAddress(&pO, g_O);
    cudaGetSymbolAddress(&pA2, g_A2);
    cudaGetSymbolAddress(&pH, g_Hm);
    cudaGetSymbolAddress(&pT, g_T);
    cudaGetSymbolAddress(&pWqkv, g_Wqkv);
    cudaGetSymbolAddress(&pWproj, g_Wproj);
    cudaGetSymbolAddress(&pWfc1, g_Wfc1);
    cudaGetSymbolAddress(&pWfc2, g_Wfc2);

    cudaFuncSetAttribute(gemm_f16_kernel<EpiQKV>, cudaFuncAttributeMaxDynamicSharedMemorySize, GEMM_SMEM);
    cudaFuncSetAttribute(gemm_f16_kernel<EpiProj>, cudaFuncAttributeMaxDynamicSharedMemorySize, GEMM_SMEM);
    cudaFuncSetAttribute(gemm_f16_kernel<EpiGelu>, cudaFuncAttributeMaxDynamicSharedMemorySize, GEMM_SMEM);
    cudaFuncSetAttribute(gemm_f16_kernel<EpiY2>, cudaFuncAttributeMaxDynamicSharedMemorySize, GEMM_SMEM);

    const int M = NTOK;

    // 1) fused prep: LN1+gather | weight f2h | bias/mask table
    prep_kernel<<<PREP_BLOCKS, 256>>>(
        x2, g1, be1, (__half*)pAwin,
        w_qkv, w_proj, w_fc1, w_fc2,
        (__half*)pWqkv, (__half*)pWproj, (__half*)pWfc1, (__half*)pWfc2,
        rpb, amask, (__half*)pT);

    // 2) QKV GEMM + fp16 scatter (Q pre-scaled by softmax_scale*log2e)
    {
        EpiQKV e{b_qkv, (__half*)pQ, (__half*)pK, (__half*)pV};
        gemm_f16_kernel<EpiQKV><<<dim3(3 * DIM / 128, M / 128), 512, GEMM_SMEM>>>(
            (const __half*)pAwin, (const __half*)pWqkv, M, 3 * DIM, DIM, e);
    }

    // 3) attention
    attn_mma_kernel<<<NWIN * HEADS / 2, 64>>>((const __half*)pQ, (const __half*)pK,
                                              (const __half*)pV, (const __half*)pT,
                                              (__half*)pO);

    // 4) proj + window reverse + residual -> y1
    {
        EpiProj e{b_proj, x1, y1};
        gemm_f16_kernel<EpiProj><<<dim3(DIM / 128, M / 128), 512, GEMM_SMEM>>>(
            (const __half*)pO, (const __half*)pWproj, M, DIM, DIM, e);
    }

    // 5) LN2(y1)
    ln_plain_kernel<<<NTOK / 8, 256>>>(y1, g2, be2, (__half*)pA2);

    // 6) FC1 + gelu
    {
        EpiGelu e{b_fc1, (__half*)pH};
        gemm_f16_kernel<EpiGelu><<<dim3(4 * DIM / 128, M / 128), 512, GEMM_SMEM>>>(
            (const __half*)pA2, (const __half*)pWfc1, M, 4 * DIM, DIM, e);
    }

    // 7) FC2 + residual -> y2
    {
        EpiY2 e{b_fc2, x2, y2};
        gemm_f16_kernel<EpiY2><<<dim3(DIM / 128, M / 128), 512, GEMM_SMEM>>>(
            (const __half*)pH, (const __half*)pWfc2, M, DIM, 4 * DIM, e);
    }
}